// round 11
// baseline (speedup 1.0000x reference)
#include <cuda_runtime.h>

// CapsNet dynamic routing. b_t = u * Vsum so u (189 MB) is never materialized.
// Warp = (d-pair, o-half): 5 output caps per warp, lanes = 32 batches, so every
// W smem read stays a single-address broadcast while per-thread register state
// halves (-> 24 warps/SM). Softmax Z exchanged between paired warps through a
// double-buffered smem slot + named barrier. f32x2 packed math; Taylor exp.

namespace {
constexpr int B_  = 256;
constexpr int IC_ = 1152;
constexpr int ID_ = 8;
constexpr int OC_ = 10;
constexpr int OH  = 5;                // o's per warp
constexpr int OD_ = 16;
constexpr int SOD = B_ * OC_ * OD_;   // 40960, layout [b][o][d]

constexpr int IBLK = 16;              // i's per smem chunk
constexpr int NCHK = 2;               // chunks per CTA (32 i total)
constexpr int BCH  = 32;              // batches per CTA (= lanes)
constexpr int NT   = 256;             // 8 warps: (dp 0..3) x (oh 0..1)
constexpr int GX   = IC_ / (IBLK * NCHK);  // 36
constexpr int GY   = B_ / BCH;             // 8
// gridDim.z = 2: each CTA covers 4 of the 8 d-pairs.

constexpr int W_TILE_F = IBLK * OC_ * (OD_ / 2) * ID_;  // 10240 floats (40 KB)
constexpr int XI = 33;                 // float4 stride over i (padded)
constexpr int XH = IBLK * XI;          // 528 float4 per k-half
constexpr int X_TILE_B = 2 * XH * 16;  // 16896 B
constexpr int Z_OFF_F  = W_TILE_F + 2 * XH * 4;   // float offset of Zbuf
constexpr int SMEMB    = W_TILE_F * 4 + X_TILE_B + 4096;  // 61952 B
constexpr int WT_ELEMS = IC_ * OC_ * OD_ * ID_;   // 1474560
}

typedef unsigned long long ull;

__device__ __align__(16) float g_Wt[WT_ELEMS];  // [i][o][dp][k][dl]
__device__ __align__(16) float g_s[3][SOD];     // [b][o][d]
__device__ __align__(16) float g_Vsum[SOD];     // running sum of squash(s)

__device__ __forceinline__ float fast_rcp(float x) {
    float y; asm("rcp.approx.ftz.f32 %0, %1;" : "=f"(y) : "f"(x)); return y;
}
__device__ __forceinline__ float fast_rsqrt(float x) {
    float y; asm("rsqrt.approx.ftz.f32 %0, %1;" : "=f"(y) : "f"(x)); return y;
}
__device__ __forceinline__ ull pack2(float lo, float hi) {
    ull r; asm("mov.b64 %0, {%1, %2};" : "=l"(r) : "f"(lo), "f"(hi)); return r;
}
__device__ __forceinline__ void unpack2(ull v, float& lo, float& hi) {
    asm("mov.b64 {%0, %1}, %2;" : "=f"(lo), "=f"(hi) : "l"(v));
}
__device__ __forceinline__ ull fma2(ull a, ull b, ull c) {
    ull d; asm("fma.rn.f32x2 %0, %1, %2, %3;" : "=l"(d) : "l"(a), "l"(b), "l"(c)); return d;
}
__device__ __forceinline__ ull mul2(ull a, ull b) {
    ull d; asm("mul.rn.f32x2 %0, %1, %2;" : "=l"(d) : "l"(a), "l"(b)); return d;
}
__device__ __forceinline__ ull add2(ull a, ull b) {
    ull d; asm("add.rn.f32x2 %0, %1, %2;" : "=l"(d) : "l"(a), "l"(b)); return d;
}
__device__ __forceinline__ void named_bar(int id) {
    asm volatile("bar.sync %0, 64;" :: "r"(id) : "memory");
}

// Transpose W[i][o][d][k] -> g_Wt[i][o][dp][k][dl], zero accumulators.
__global__ void prepack_zero_kernel(const float* __restrict__ W) {
    int e = blockIdx.x * 512 + threadIdx.x;
    if (e < SOD) {
        g_s[0][e] = 0.f; g_s[1][e] = 0.f; g_s[2][e] = 0.f;
        g_Vsum[e] = 0.f;
    }
    if (e < WT_ELEMS) {
        int io = e >> 7;          // 128 floats per (i,o)
        int r  = e & 127;
        int dp = r >> 4;
        int k  = (r >> 1) & 7;
        int dl = r & 1;
        g_Wt[e] = W[(io * OD_ + 2 * dp + dl) * ID_ + k];
    }
}

// Routing pass. Grid (36, 8, 2), block 256 = 8 warps.
// warp w: dp_local = w>>1 (0..3), oh = w&1; lane = batch.
template<bool FIRST>
__global__ __launch_bounds__(NT, 3) void route_kernel(
    const float* __restrict__ x,   // [B, IC, ID]
    int which)
{
    extern __shared__ float sm[];
    float* Wsm = sm;                                        // 40 KB
    float4* X4 = reinterpret_cast<float4*>(sm + W_TILE_F);  // [h][i(pad)][b]
    ull* Zbuf  = reinterpret_cast<ull*>(sm + Z_OFF_F);      // [buf][dp][oh][bl]

    const int t     = threadIdx.x;
    const int w     = t >> 5;       // warp 0..7
    const int bl    = t & 31;       // lane = batch within chunk
    const int dp_l  = w >> 1;       // 0..3
    const int oh    = w & 1;        // 0..1
    const int obase = oh * OH;
    const int dp    = blockIdx.z * 4 + dp_l;   // global d-pair 0..7
    const int b0    = blockIdx.y * BCH;
    const int b     = b0 + bl;
    const int barid = 1 + dp_l;

    // loop-invariant softmax logit scale pairs (Vsum for d = 2dp, 2dp+1)
    ull Vp[OH];
    if (!FIRST) {
#pragma unroll
        for (int j = 0; j < OH; j++)
            Vp[j] = *reinterpret_cast<const ull*>(
                g_Vsum + (((size_t)b * OC_ + obase + j) * OD_ + 2 * dp));
    }

    ull s[OH];
    const ull zz  = pack2(0.f, 0.f);
    const ull ONE = pack2(1.f, 1.f);
    const ull C12 = pack2(0.5f, 0.5f);
    const ull C16 = pack2(1.f / 6.f, 1.f / 6.f);
#pragma unroll
    for (int j = 0; j < OH; j++) s[j] = zz;

    for (int c = 0; c < NCHK; c++) {
        const int i0 = blockIdx.x * (IBLK * NCHK) + c * IBLK;
        if (c) __syncthreads();     // drain readers of previous tiles

        // ---- W tile: this CTA's d-half of the pre-transposed weights ----
        {
            // per (i,o): 128 floats = 32 float4; our half = 16 float4
            const float4* src = reinterpret_cast<const float4*>(g_Wt)
                                + (size_t)i0 * 320 + blockIdx.z * 16;
            float4* dst = reinterpret_cast<float4*>(Wsm);
#pragma unroll
            for (int r = 0; r < W_TILE_F / 4 / NT; r++) {  // 10
                int e4 = t + r * NT;
                int io = e4 >> 4;
                int q  = e4 & 15;
                dst[e4] = src[io * 32 + q];
            }
        }
        // ---- x tile: [h][i][b] float4, padded strides ----
        {
#pragma unroll
            for (int r = 0; r < 4; r++) {
                int f  = t + r * NT;                      // 0..1023
                int bb = f >> 5;                          // 0..31
                int cc = f & 31;
                const float4* src = reinterpret_cast<const float4*>(
                    x + ((size_t)(b0 + bb) * IC_ + i0) * ID_);
                int i = cc >> 1, h = cc & 1;
                X4[h * XH + i * XI + bb] = src[cc];
            }
        }
        __syncthreads();

        const ulonglong2* W2 = reinterpret_cast<const ulonglong2*>(Wsm);

#pragma unroll 4
        for (int i = 0; i < IBLK; i++) {
            float4 xa = X4[i * XI + bl];
            float4 xb = X4[XH + i * XI + bl];
            ull xp[ID_];
            xp[0] = pack2(xa.x, xa.x); xp[1] = pack2(xa.y, xa.y);
            xp[2] = pack2(xa.z, xa.z); xp[3] = pack2(xa.w, xa.w);
            xp[4] = pack2(xb.x, xb.x); xp[5] = pack2(xb.y, xb.y);
            xp[6] = pack2(xb.z, xb.z); xp[7] = pack2(xb.w, xb.w);

            ull u[OH];
#pragma unroll
            for (int j = 0; j < OH; j++) {
                // broadcast LDS.128: all 32 lanes read the same address
                int wb = ((i * OC_ + obase + j) * 4 + dp_l) * 4;
                ulonglong2 w01 = W2[wb];
                ulonglong2 w23 = W2[wb + 1];
                ulonglong2 w45 = W2[wb + 2];
                ulonglong2 w67 = W2[wb + 3];
                ull acc = mul2(w01.x, xp[0]);
                acc = fma2(w01.y, xp[1], acc);
                acc = fma2(w23.x, xp[2], acc);
                acc = fma2(w23.y, xp[3], acc);
                acc = fma2(w45.x, xp[4], acc);
                acc = fma2(w45.y, xp[5], acc);
                acc = fma2(w67.x, xp[6], acc);
                acc = fma2(w67.y, xp[7], acc);
                u[j] = acc;
            }

            if (FIRST) {
#pragma unroll
                for (int j = 0; j < OH; j++) s[j] = add2(s[j], u[j]);
            } else {
                ull Zh = zz;
#pragma unroll
                for (int j = 0; j < OH; j++) {
                    // z = u*Vsum is tiny (|z| < ~0.15): cubic Taylor exp,
                    // all on the FMA pipe, fully packed.
                    ull z = mul2(u[j], Vp[j]);
                    ull p = fma2(z, C16, C12);
                    p = fma2(z, p, ONE);
                    ull e = fma2(z, p, ONE);
                    Zh = add2(Zh, e);
                    u[j] = mul2(u[j], e);         // u now holds u*e
                }
                // exchange Z with partner warp (other o-half), double-buffered
                int slot = (((i & 1) * 4 + dp_l) * 2 + oh) * 32 + bl;
                Zbuf[slot] = Zh;
                named_bar(barid);                 // BAR drains the STS
                ull Zo = Zbuf[(((i & 1) * 4 + dp_l) * 2 + (oh ^ 1)) * 32 + bl];
                ull Z2 = add2(Zh, Zo);
                float Z0, Z1; unpack2(Z2, Z0, Z1);
                ull rp = pack2(fast_rcp(Z0), fast_rcp(Z1));
#pragma unroll
                for (int j = 0; j < OH; j++) s[j] = fma2(u[j], rp, s[j]);
            }
        }
    }

    // accumulate partial s into global [b][o][d]
    float* sp = g_s[which] + ((size_t)b * OC_ + obase) * OD_ + 2 * dp;
#pragma unroll
    for (int j = 0; j < OH; j++) {
        float a0, a1; unpack2(s[j], a0, a1);
        if (FIRST) { a0 *= (1.0f / OC_); a1 *= (1.0f / OC_); }
        atomicAdd(sp + j * OD_, a0);
        atomicAdd(sp + j * OD_ + 1, a1);
    }
}

// squash(s) per (b,o) over d; update Vsum, or write final output.
__global__ void squash_kernel(int which, float* __restrict__ out, int final_) {
    const float* __restrict__ s = g_s[which];
    int t  = blockIdx.x * 256 + threadIdx.x;   // SOD threads exactly
    int d  = t & 15;
    int bo = t >> 4;
    int idx = bo * OD_ + d;                    // [b][o][d]

    float sv = s[idx];
    float l2 = sv * sv;
#pragma unroll
    for (int off = 8; off > 0; off >>= 1)
        l2 += __shfl_xor_sync(0xffffffffu, l2, off);

    float coef = l2 * fast_rsqrt(l2) * fast_rcp(1.f + l2);
    float v = sv * coef;

    if (final_) {
        out[idx] = v;                           // output [B, OC, OD]
    } else {
        g_Vsum[idx] = g_Vsum[idx] + v;
    }
}

extern "C" void kernel_launch(void* const* d_in, const int* in_sizes, int n_in,
                              void* d_out, int out_size) {
    const float* x = (const float*)d_in[0];   // [256,1152,8]
    const float* W = (const float*)d_in[1];   // [1152,10,16,8]
    float* out = (float*)d_out;               // [256,10,16]

    cudaFuncSetAttribute(route_kernel<true>,
                         cudaFuncAttributeMaxDynamicSharedMemorySize, SMEMB);
    cudaFuncSetAttribute(route_kernel<false>,
                         cudaFuncAttributeMaxDynamicSharedMemorySize, SMEMB);

    dim3 rg(GX, GY, 2);
    int sgrid = SOD / 256;   // 160

    prepack_zero_kernel<<<(WT_ELEMS + 511) / 512, 512>>>(W);

    route_kernel<true><<<rg, NT, SMEMB>>>(x, 0);
    squash_kernel<<<sgrid, 256>>>(0, out, 0);

    route_kernel<false><<<rg, NT, SMEMB>>>(x, 1);
    squash_kernel<<<sgrid, 256>>>(1, out, 0);

    route_kernel<false><<<rg, NT, SMEMB>>>(x, 2);
    squash_kernel<<<sgrid, 256>>>(2, out, 1);
}